// round 5
// baseline (speedup 1.0000x reference)
#include <cuda_runtime.h>
#include <math.h>

constexpr int Bc=4, Sc=512, Dc=512, Ic=1024, Cc=32, NCc=16;
constexpr long long SD=(long long)Sc*Dc;
constexpr long long ID=(long long)Ic*Dc;
constexpr long long CI=(long long)Cc*Ic;
constexpr long long CD=(long long)Cc*Dc;
constexpr long long SI=(long long)Sc*Ic;

// ---------------- persistent device scratch ----------------
__device__ float g_k[Bc*Sc*Dc];
__device__ float g_v[Bc*Sc*Dc];
__device__ float g_q[Bc*Sc*Dc];
__device__ float g_theta[Bc*Sc];
__device__ float g_alpha[Bc*Sc];
__device__ float g_eta[Bc*Sc];
__device__ float g_MW1[Bc*Ic*Dc];
__device__ float g_SW1[Bc*Ic*Dc];
__device__ float g_MW2[Bc*Dc*Ic];
__device__ float g_SW2[Bc*Dc*Ic];
__device__ float g_Mln[Bc*Dc];
__device__ float g_Sln[Bc*Dc];
__device__ float g_z[Bc*Cc*Ic];
__device__ float g_h[Bc*Cc*Ic];
__device__ float g_o[Bc*Cc*Dc];
__device__ float g_do[Bc*Cc*Dc];
__device__ float g_gln[Bc*Cc*Dc];
__device__ float g_p[Bc*Cc*Ic];
__device__ float g_nk[Bc*Cc], g_ndo[Bc*Cc], g_ngl[Bc*Cc], g_nh[Bc*Cc];
__device__ float g_npp[Bc*Cc*16];
__device__ float g_sE[Bc*Cc], g_sc2[Bc*Cc];
__device__ float g_Ab[Bc], g_Bpb[Bc], g_cSb[Bc];
__device__ float g_hbuf[Bc*Sc*Ic];
__device__ float g_obuf[Bc*Sc*Dc];
__device__ int g_barCount;   // zero-init, returns to 0 after each barrier
__device__ int g_barGen;     // monotonically increasing (wraps OK)

__device__ __forceinline__ float sigmoidf(float v){ return 1.f/(1.f+expf(-v)); }

// ---------------- grid-wide barrier (all nb blocks guaranteed resident) ----------------
__device__ __forceinline__ void gridSync(int nb){
    __syncthreads();
    if(threadIdx.x==0){
        int gen = *((volatile int*)&g_barGen);
        __threadfence();
        if(atomicAdd(&g_barCount, 1) == nb-1){
            g_barCount = 0;
            __threadfence();
            atomicExch(&g_barGen, gen+1);
        } else {
            while(*((volatile int*)&g_barGen) == gen){ __nanosleep(40); }
            __threadfence();
        }
    }
    __syncthreads();
}

// ---------------- 512-thread block reduce ----------------
__device__ __forceinline__ float blockReduce(float v, float* sred){
    int lane = threadIdx.x & 31, w = threadIdx.x >> 5;
    #pragma unroll
    for(int o=16;o>0;o>>=1) v += __shfl_down_sync(0xffffffffu, v, o);
    if(lane==0) sred[w] = v;
    __syncthreads();
    if(w==0){
        float r = (lane < 16) ? sred[lane] : 0.f;
        #pragma unroll
        for(int o=8;o>0;o>>=1) r += __shfl_down_sync(0xffffffffu, r, o);
        if(lane==0) sred[32] = r;
    }
    __syncthreads();
    float r = sred[32];
    __syncthreads();
    return r;
}

// ---------------- NT tile 128x64, 512 threads. C[128,64] = A[128,K] @ B[64,K]^T ----------------
// mode 0: store, 1: silu
__device__ void nt128(const float* __restrict__ A, const float* __restrict__ B,
                      float* __restrict__ C, int K, int ldc, int mode, float* SH){
    float* As = SH;            // [32 kk][132] holds m
    float* Bs = SH + 4224;     // [32 kk][68] holds n
    const int tid = threadIdx.x;
    const int ty = tid>>4, tx = tid&15;      // rows ty*4..+3, cols tx*4..+3
    float acc[4][4];
    #pragma unroll
    for(int i=0;i<4;i++){ acc[i][0]=0.f; acc[i][1]=0.f; acc[i][2]=0.f; acc[i][3]=0.f; }
    const int am = tid>>2, akb = (tid&3)*8;
    const int bn = tid>>3, bkb = (tid&7)*4;
    for(int k0=0;k0<K;k0+=32){
        const float* ap = A + (long long)am*K + k0 + akb;
        float4 v0 = *(const float4*)ap;
        float4 v1 = *(const float4*)(ap+4);
        As[(akb+0)*132+am]=v0.x; As[(akb+1)*132+am]=v0.y; As[(akb+2)*132+am]=v0.z; As[(akb+3)*132+am]=v0.w;
        As[(akb+4)*132+am]=v1.x; As[(akb+5)*132+am]=v1.y; As[(akb+6)*132+am]=v1.z; As[(akb+7)*132+am]=v1.w;
        const float* bp = B + (long long)bn*K + k0 + bkb;
        float4 w = *(const float4*)bp;
        Bs[(bkb+0)*68+bn]=w.x; Bs[(bkb+1)*68+bn]=w.y; Bs[(bkb+2)*68+bn]=w.z; Bs[(bkb+3)*68+bn]=w.w;
        __syncthreads();
        #pragma unroll
        for(int kk=0;kk<32;kk++){
            float4 a = *(float4*)&As[kk*132 + ty*4];
            float4 b = *(float4*)&Bs[kk*68 + tx*4];
            acc[0][0]+=a.x*b.x; acc[0][1]+=a.x*b.y; acc[0][2]+=a.x*b.z; acc[0][3]+=a.x*b.w;
            acc[1][0]+=a.y*b.x; acc[1][1]+=a.y*b.y; acc[1][2]+=a.y*b.z; acc[1][3]+=a.y*b.w;
            acc[2][0]+=a.z*b.x; acc[2][1]+=a.z*b.y; acc[2][2]+=a.z*b.z; acc[2][3]+=a.z*b.w;
            acc[3][0]+=a.w*b.x; acc[3][1]+=a.w*b.y; acc[3][2]+=a.w*b.z; acc[3][3]+=a.w*b.w;
        }
        __syncthreads();
    }
    #pragma unroll
    for(int i=0;i<4;i++){
        int r = ty*4+i;
        float4 o4;
        o4.x=acc[i][0]; o4.y=acc[i][1]; o4.z=acc[i][2]; o4.w=acc[i][3];
        if(mode==1){
            o4.x *= sigmoidf(o4.x); o4.y *= sigmoidf(o4.y);
            o4.z *= sigmoidf(o4.z); o4.w *= sigmoidf(o4.w);
        }
        *(float4*)&C[(long long)r*ldc + tx*4] = o4;
    }
}

// ---------------- NT tile 32x64, 512 threads. mode 0: store, 2: Z raw + silu C ----------------
__device__ void nt32(const float* __restrict__ A, const float* __restrict__ B,
                     float* __restrict__ C, float* __restrict__ Z,
                     int K, int ldc, int mode, float* SH){
    float* As = SH;            // [32 kk][36] holds m (32)
    float* Bs = SH + 1152;     // [32 kk][68] holds n (64)
    const int tid = threadIdx.x;
    const int ty = tid>>4, tx = tid&15;  // row ty, cols tx*4
    float acc[4] = {0.f,0.f,0.f,0.f};
    const int bn = tid>>3, bkb = (tid&7)*4;
    for(int k0=0;k0<K;k0+=32){
        if(tid<256){
            int m = tid>>3, kb = (tid&7)*4;
            float4 v = *(const float4*)(A + (long long)m*K + k0 + kb);
            As[(kb+0)*36+m]=v.x; As[(kb+1)*36+m]=v.y; As[(kb+2)*36+m]=v.z; As[(kb+3)*36+m]=v.w;
        }
        {
            float4 w = *(const float4*)(B + (long long)bn*K + k0 + bkb);
            Bs[(bkb+0)*68+bn]=w.x; Bs[(bkb+1)*68+bn]=w.y; Bs[(bkb+2)*68+bn]=w.z; Bs[(bkb+3)*68+bn]=w.w;
        }
        __syncthreads();
        #pragma unroll
        for(int kk=0;kk<32;kk++){
            float a = As[kk*36+ty];
            float4 b = *(float4*)&Bs[kk*68+tx*4];
            acc[0]+=a*b.x; acc[1]+=a*b.y; acc[2]+=a*b.z; acc[3]+=a*b.w;
        }
        __syncthreads();
    }
    long long base = (long long)ty*ldc + tx*4;
    if(mode==2){
        float4 z4; z4.x=acc[0]; z4.y=acc[1]; z4.z=acc[2]; z4.w=acc[3];
        *(float4*)&Z[base] = z4;
        float4 h4;
        h4.x=acc[0]*sigmoidf(acc[0]); h4.y=acc[1]*sigmoidf(acc[1]);
        h4.z=acc[2]*sigmoidf(acc[2]); h4.w=acc[3]*sigmoidf(acc[3]);
        *(float4*)&C[base] = h4;
    } else {
        float4 o4; o4.x=acc[0]; o4.y=acc[1]; o4.z=acc[2]; o4.w=acc[3];
        *(float4*)&C[base] = o4;
    }
}

// ---------------- NN tile 32x64: P = (A@B) * dsilu(Z); also write |p|^2 row partials ----------------
__device__ void nn32_p(const float* __restrict__ A, const float* __restrict__ B,
                       const float* __restrict__ Z, float* __restrict__ P,
                       int K, int N, int ld, int b, int jtile, float* SH){
    float* As = SH;            // [32 kk][36]
    float* Bs = SH + 1152;     // [32 kk][68]
    const int tid = threadIdx.x;
    const int ty = tid>>4, tx = tid&15;
    float acc[4] = {0.f,0.f,0.f,0.f};
    const int bkk = tid>>4, bnb = (tid&15)*4;
    for(int k0=0;k0<K;k0+=32){
        if(tid<256){
            int m = tid>>3, kb = (tid&7)*4;
            float4 v = *(const float4*)(A + (long long)m*K + k0 + kb);
            As[(kb+0)*36+m]=v.x; As[(kb+1)*36+m]=v.y; As[(kb+2)*36+m]=v.z; As[(kb+3)*36+m]=v.w;
        }
        {
            float4 w = *(const float4*)(B + (long long)(k0+bkk)*N + bnb);
            *(float4*)&Bs[bkk*68+bnb] = w;
        }
        __syncthreads();
        #pragma unroll
        for(int kk=0;kk<32;kk++){
            float a = As[kk*36+ty];
            float4 b4 = *(float4*)&Bs[kk*68+tx*4];
            acc[0]+=a*b4.x; acc[1]+=a*b4.y; acc[2]+=a*b4.z; acc[3]+=a*b4.w;
        }
        __syncthreads();
    }
    long long base = (long long)ty*ld + tx*4;
    float4 z4 = *(const float4*)&Z[base];
    float p0,p1,p2,p3;
    { float s=sigmoidf(z4.x); p0=acc[0]*(s*(1.f+z4.x*(1.f-s))); }
    { float s=sigmoidf(z4.y); p1=acc[1]*(s*(1.f+z4.y*(1.f-s))); }
    { float s=sigmoidf(z4.z); p2=acc[2]*(s*(1.f+z4.z*(1.f-s))); }
    { float s=sigmoidf(z4.w); p3=acc[3]*(s*(1.f+z4.w*(1.f-s))); }
    float4 o4; o4.x=p0; o4.y=p1; o4.z=p2; o4.w=p3;
    *(float4*)&P[base] = o4;
    // row partial of |p|^2 over this 64-col tile: reduce across the 16 lanes of the row
    float part = p0*p0 + p1*p1 + p2*p2 + p3*p3;
    #pragma unroll
    for(int o=8;o>0;o>>=1) part += __shfl_xor_sync(0xffffffffu, part, o);
    if(tx==0) g_npp[(b*Cc+ty)*16 + jtile] = part;
}

// ---------------- clip coefs into shared (scf[0..31]=ce, scf[32..63]=cc) ----------------
__device__ void loadCoefs(int b, float* scf){
    const int tid = threadIdx.x;
    if(tid < 32){
        int t = tid;
        float np = 0.f;
        #pragma unroll
        for(int j=0;j<16;j++) np += g_npp[(b*Cc+t)*16 + j];
        float sq = np*g_nk[b*Cc+t] + g_ndo[b*Cc+t]*g_nh[b*Cc+t] + g_ngl[b*Cc+t];
        float coef = fminf(1.f/(sqrtf(sq)+1e-6f), 1.f);
        scf[t]    = g_sE[b*Cc+t]*coef;
        scf[32+t] = g_sc2[b*Cc+t]*coef;
    }
    __syncthreads();
}

// ---------------- rank-32 tile 64x64: S' = A*S - sum ce*p*k ; M' = Bp*M + cS*S - sum cc*p*k ----------------
__device__ void rankTile(float* __restrict__ Sm, float* __restrict__ Mm, int ldS,
                         const float* __restrict__ P, long long pStride,
                         const float* __restrict__ Kv, long long kStride,
                         const float* scf, float Acf, float Bp, float cS, float* SH){
    float* Ps = SH;            // [32 t][68]
    float* Ks = SH + 2176;
    const int tid = threadIdx.x;
    {
        int t = tid>>4, cb = (tid&15)*4;
        *(float4*)&Ps[t*68+cb] = *(const float4*)(P + (long long)t*pStride + cb);
        *(float4*)&Ks[t*68+cb] = *(const float4*)(Kv + (long long)t*kStride + cb);
    }
    __syncthreads();
    const int ty = tid>>4, tx = tid&15;   // rows ty*2..+1, cols tx*4..+3
    float ae[2][4]={{0.f,0.f,0.f,0.f},{0.f,0.f,0.f,0.f}};
    float ac[2][4]={{0.f,0.f,0.f,0.f},{0.f,0.f,0.f,0.f}};
    #pragma unroll
    for(int t=0;t<32;t++){
        float ce = scf[t], cc = scf[32+t];
        float p0 = Ps[t*68 + ty*2], p1 = Ps[t*68 + ty*2 + 1];
        float4 k4 = *(float4*)&Ks[t*68 + tx*4];
        float e0=ce*p0, e1=ce*p1, c0=cc*p0, c1=cc*p1;
        ae[0][0]+=e0*k4.x; ae[0][1]+=e0*k4.y; ae[0][2]+=e0*k4.z; ae[0][3]+=e0*k4.w;
        ae[1][0]+=e1*k4.x; ae[1][1]+=e1*k4.y; ae[1][2]+=e1*k4.z; ae[1][3]+=e1*k4.w;
        ac[0][0]+=c0*k4.x; ac[0][1]+=c0*k4.y; ac[0][2]+=c0*k4.z; ac[0][3]+=c0*k4.w;
        ac[1][0]+=c1*k4.x; ac[1][1]+=c1*k4.y; ac[1][2]+=c1*k4.z; ac[1][3]+=c1*k4.w;
    }
    #pragma unroll
    for(int i=0;i<2;i++){
        long long base = (long long)(ty*2+i)*ldS + tx*4;
        float4 s4 = *(float4*)&Sm[base];
        float4 m4 = *(float4*)&Mm[base];
        float4 ns, nm;
        ns.x = Acf*s4.x - ae[i][0]; nm.x = Bp*m4.x + cS*s4.x - ac[i][0];
        ns.y = Acf*s4.y - ae[i][1]; nm.y = Bp*m4.y + cS*s4.y - ac[i][1];
        ns.z = Acf*s4.z - ae[i][2]; nm.z = Bp*m4.z + cS*s4.z - ac[i][2];
        ns.w = Acf*s4.w - ae[i][3]; nm.w = Bp*m4.w + cS*s4.w - ac[i][3];
        *(float4*)&Sm[base] = ns;
        *(float4*)&Mm[base] = nm;
    }
    __syncthreads();
}

// ==================== THE MEGA KERNEL ====================
__global__ __launch_bounds__(512, 1) void mega_kernel(
    const float* __restrict__ x,  const float* __restrict__ wq, const float* __restrict__ wk,
    const float* __restrict__ wv, const float* __restrict__ qn, const float* __restrict__ kn,
    const float* __restrict__ alw,const float* __restrict__ thw,const float* __restrict__ etw,
    const float* __restrict__ w1, const float* __restrict__ w2, const float* __restrict__ lnw,
    float* __restrict__ out, int nb)
{
    __shared__ float SH[6400];
    __shared__ float sred[33];
    __shared__ float scf[96];
    const int bid = blockIdx.x, tid = threadIdx.x;

    // ---------- Phase 0: state init + gates ----------
    {
        const float4* w1_4 = (const float4*)w1;
        const float4* w2_4 = (const float4*)w2;
        float4 zero4; zero4.x=0.f; zero4.y=0.f; zero4.z=0.f; zero4.w=0.f;
        for(long long i4 = (long long)bid*512 + tid; i4 < ID/4; i4 += (long long)nb*512){
            float4 a = w1_4[i4], b2 = w2_4[i4];
            #pragma unroll
            for(int b=0;b<Bc;b++){
                ((float4*)g_MW1)[b*(ID/4) + i4] = a;
                ((float4*)g_SW1)[b*(ID/4) + i4] = zero4;
                ((float4*)g_MW2)[b*(ID/4) + i4] = b2;
                ((float4*)g_SW2)[b*(ID/4) + i4] = zero4;
            }
        }
        for(int i = bid*512 + tid; i < Dc; i += nb*512){
            float l = lnw[i];
            #pragma unroll
            for(int b=0;b<Bc;b++){ g_Mln[b*Dc+i] = l; g_Sln[b*Dc+i] = 0.f; }
        }
        // gates: warp per token
        int wid = tid>>5, lane = tid&31;
        for(int task = bid; task < 128; task += nb){
            int tok = task*16 + wid;
            const float* xr = x + (long long)tok*Dc;
            float st=0.f, sa=0.f, se=0.f;
            for(int j=lane; j<Dc; j+=32){
                float xv = xr[j];
                st += xv*thw[j]; sa += xv*alw[j]; se += xv*etw[j];
            }
            #pragma unroll
            for(int o=16;o>0;o>>=1){
                st += __shfl_down_sync(0xffffffffu, st, o);
                sa += __shfl_down_sync(0xffffffffu, sa, o);
                se += __shfl_down_sync(0xffffffffu, se, o);
            }
            if(lane==0){
                g_theta[tok] = 0.01f*sigmoidf(st);
                g_alpha[tok] = sigmoidf(sa);
                g_eta[tok]   = sigmoidf(se);
            }
        }
    }
    gridSync(nb);

    // ---------- Phase 1: projections k, v, q ----------
    for(int task = bid; task < 384; task += nb){
        int w = task >> 7, tile = task & 127;
        int mt = tile >> 3, nt = tile & 7;
        const float* W = (w==0) ? wk : ((w==1) ? wv : wq);
        float* dst = (w==0) ? g_k : ((w==1) ? g_v : g_q);
        nt128(x + (long long)mt*128*Dc, W + (long long)nt*64*Dc,
              dst + (long long)mt*128*Dc + nt*64, Dc, Dc, 0, SH);
    }
    gridSync(nb);

    // ---------- Phase 2: activations (silu / silu+rms) ----------
    for(int task = bid; task < 3*Bc*Sc; task += nb){
        int which = task / (Bc*Sc), row = task % (Bc*Sc);
        float* buf = (which==0) ? g_k : ((which==1) ? g_v : g_q);
        long long idx = (long long)row*Dc + tid;
        float v = buf[idx];
        float sv = v*sigmoidf(v);
        if(which==1){ buf[idx] = sv; }
        else{
            const float* wnorm = (which==0) ? kn : qn;
            float s2 = blockReduce(sv*sv, sred);
            float n = rsqrtf(s2*(1.f/Dc) + 1e-6f);
            buf[idx] = sv*n*wnorm[tid];
        }
    }
    gridSync(nb);

    // ---------- chunk loop ----------
    for(int ci=0; ci<NCc; ci++){
        // PA: z/h = (silu)(Kc @ W1^T)   tasks: 4b x 16 ntiles
        for(int task = bid; task < 64; task += nb){
            int b = task >> 4, nt = task & 15;
            nt32(g_k + ((long long)b*Sc + ci*Cc)*Dc,
                 g_MW1 + (long long)b*ID + (long long)nt*64*Dc,
                 g_h + (long long)b*CI + nt*64,
                 g_z + (long long)b*CI + nt*64,
                 Dc, Ic, 2, SH);
        }
        gridSync(nb);

        // PB: o = H @ W2^T   tasks: 4b x 8
        for(int task = bid; task < 32; task += nb){
            int b = task >> 3, nt = task & 7;
            nt32(g_h + (long long)b*CI,
                 g_MW2 + (long long)b*ID + (long long)nt*64*Ic,
                 g_o + (long long)b*CD + nt*64, nullptr,
                 Ic, Dc, 0, SH);
        }
        gridSync(nb);

        // PC: per-token backward through rms head; norms; scan-coef recurrence
        for(int task = bid; task < Bc*Cc; task += nb){
            int b = task >> 5, t = task & 31;
            int tok = ci*Cc + t;
            int d = tid;
            float kv = g_k[((long long)b*Sc + tok)*Dc + d];
            float vv = g_v[((long long)b*Sc + tok)*Dc + d];
            float ov = g_o[((long long)b*Cc + t)*Dc + d];
            float ln = g_Mln[b*Dc + d];
            float th = g_theta[b*Sc + tok];
            float s2 = blockReduce(ov*ov, sred);
            float n = rsqrtf(s2*(1.f/Dc) + 1e-6f);
            float y = ln*n*ov;
            float r = kv + y - vv;
            float u = (2.f/Dc)*th*r;
            float gl = u*n*ov;
            float ws = blockReduce(u*ov*ln, sred);
            float dov = n*ln*u - (n*n*n*ov*(1.f/Dc))*ws;
            g_do[((long long)b*Cc + t)*Dc + d] = dov;
            g_gln[((long long)b*Cc + t)*Dc + d] = gl;
            float hv0 = g_h[((long long)b*Cc + t)*Ic + d];
            float hv1 = g_h[((long long)b*Cc + t)*Ic + d + 512];
            float nk = blockReduce(kv*kv, sred);
            float nd = blockReduce(dov*dov, sred);
            float ng = blockReduce(gl*gl, sred);
            float nh = blockReduce(hv0*hv0 + hv1*hv1, sred);
            if(d==0){
                g_nk[b*Cc+t]=nk; g_ndo[b*Cc+t]=nd; g_ngl[b*Cc+t]=ng; g_nh[b*Cc+t]=nh;
            }
            if(t==0){
                // serial suffix recurrence for this batch
                if(tid < 32){
                    scf[tid]    = g_eta[b*Sc + ci*Cc + tid];
                    scf[32+tid] = 1.f - g_alpha[b*Sc + ci*Cc + tid];
                }
                __syncthreads();
                if(tid==0){
                    float E=1.f, F=1.f, c=1.f, cSv=0.f;
                    for(int s=Cc-1;s>=0;s--){
                        g_sE[b*Cc+s] = E;
                        g_sc2[b*Cc+s] = c;
                        if(s==0) cSv = scf[0]*c;
                        float Fn = scf[32+s]*F;
                        c = Fn + scf[s]*c;
                        E = scf[s]*E;
                        F = Fn;
                    }
                    g_Ab[b]=E; g_Bpb[b]=F; g_cSb[b]=cSv;
                }
                __syncthreads();
            }
        }
        gridSync(nb);

        // PD: p = (DO @ W2) * dsilu(z)  + |p|^2 partials   tasks: 4b x 16
        for(int task = bid; task < 64; task += nb){
            int b = task >> 4, nt = task & 15;
            nn32_p(g_do + (long long)b*CD,
                   g_MW2 + (long long)b*ID + nt*64,
                   g_z + (long long)b*CI + nt*64,
                   g_p + (long long)b*CI + nt*64,
                   Dc, Ic, Ic, b, nt, SH);
        }
        gridSync(nb);

        // PF: ln update (tasks 0..3) + rank updates W1 (4..515) + W2 (516..1027)
        for(int task = bid; task < 1028; task += nb){
            if(task < 4){
                int b = task;
                loadCoefs(b, scf);
                float Acf=g_Ab[b], Bp=g_Bpb[b], cS=g_cSb[b];
                int d = tid;
                float S = g_Sln[b*Dc+d], M = g_Mln[b*Dc+d];
                float se_=0.f, sc_=0.f;
                #pragma unroll
                for(int t=0;t<Cc;t++){
                    float g = g_gln[((long long)b*Cc + t)*Dc + d];
                    se_ += scf[t]*g;
                    sc_ += scf[32+t]*g;
                }
                g_Sln[b*Dc+d] = Acf*S - se_;
                g_Mln[b*Dc+d] = Bp*M + cS*S - sc_;
                __syncthreads();
            } else if(task < 516){
                int u = task - 4;
                int b = u >> 7, tile = u & 127;
                int rt = tile >> 3, ct = tile & 7;
                loadCoefs(b, scf);
                rankTile(g_SW1 + (long long)b*ID + (long long)rt*64*Dc + ct*64,
                         g_MW1 + (long long)b*ID + (long long)rt*64*Dc + ct*64, Dc,
                         g_p + (long long)b*CI + rt*64, Ic,
                         g_k + ((long long)b*Sc + ci*Cc)*Dc + ct*64, Dc,
                         scf, g_Ab[b], g_Bpb[b], g_cSb[b], SH);
            } else {
                int u = task - 516;
                int b = u >> 7, tile = u & 127;
                int rt = tile >> 4, ct = tile & 15;
                loadCoefs(b, scf);
                rankTile(g_SW2 + (long long)b*ID + (long long)rt*64*Ic + ct*64,
                         g_MW2 + (long long)b*ID + (long long)rt*64*Ic + ct*64, Ic,
                         g_do + (long long)b*CD + rt*64, Dc,
                         g_h + (long long)b*CI + ct*64, Ic,
                         scf, g_Ab[b], g_Bpb[b], g_cSb[b], SH);
            }
        }
        gridSync(nb);
    }

    // ---------- Phase 4: retrieval h = silu(q @ W1^T) ----------
    for(int task = bid; task < 256; task += nb){
        int b = task >> 6, tl = task & 63;
        int mt = tl >> 4, nt = tl & 15;
        nt128(g_q + (long long)b*SD + (long long)mt*128*Dc,
              g_MW1 + (long long)b*ID + (long long)nt*64*Dc,
              g_hbuf + (long long)b*SI + (long long)mt*128*Ic + nt*64,
              Dc, Ic, 1, SH);
    }
    gridSync(nb);

    // ---------- Phase 5: obuf = hbuf @ W2^T ----------
    for(int task = bid; task < 128; task += nb){
        int b = task >> 5, tl = task & 31;
        int mt = tl >> 3, nt = tl & 7;
        nt128(g_hbuf + (long long)b*SI + (long long)mt*128*Ic,
              g_MW2 + (long long)b*ID + (long long)nt*64*Ic,
              g_obuf + (long long)b*SD + (long long)mt*128*Dc + nt*64,
              Ic, Dc, 0, SH);
    }
    gridSync(nb);

    // ---------- Phase 6: final combine ----------
    for(int task = bid; task < Bc*Sc; task += nb){
        int b = task >> 9;
        long long idx = (long long)task*Dc + tid;
        float qv = g_q[idx];
        float ov = g_obuf[idx];
        float ln = g_Mln[b*Dc + tid];
        float s2 = blockReduce(ov*ov, sred);
        float n = rsqrtf(s2*(1.f/Dc) + 1e-6f);
        out[idx] = qv + ov*n*ln;
    }
}

extern "C" void kernel_launch(void* const* d_in, const int* in_sizes, int n_in,
                              void* d_out, int out_size){
    const float* x   = (const float*)d_in[0];
    const float* wq  = (const float*)d_in[1];
    const float* wk  = (const float*)d_in[2];
    const float* wv  = (const float*)d_in[3];
    const float* qn  = (const float*)d_in[4];
    const float* kn  = (const float*)d_in[5];
    const float* alw = (const float*)d_in[6];
    const float* thw = (const float*)d_in[7];
    const float* etw = (const float*)d_in[8];
    const float* w1  = (const float*)d_in[9];
    const float* w2  = (const float*)d_in[10];
    const float* lnw = (const float*)d_in[11];
    float* out = (float*)d_out;

    int nsm = 0;
    cudaDeviceGetAttribute(&nsm, cudaDevAttrMultiProcessorCount, 0);
    if(nsm <= 0) nsm = 148;

    mega_kernel<<<nsm, 512>>>(x, wq, wk, wv, qn, kn, alw, thw, etw, w1, w2, lnw, out, nsm);
}

// round 7
// speedup vs baseline: 1.5045x; 1.5045x over previous
#include <cuda_runtime.h>
#include <math.h>

constexpr int Bc=4, Sc=512, Dc=512, Ic=1024, Cc=32, NCc=16;
constexpr long long SD=(long long)Sc*Dc;
constexpr long long ID=(long long)Ic*Dc;
constexpr long long CI=(long long)Cc*Ic;
constexpr long long CD=(long long)Cc*Dc;
constexpr long long SI=(long long)Sc*Ic;

// ---------------- persistent device scratch ----------------
__device__ float g_k[Bc*Sc*Dc];
__device__ float g_v[Bc*Sc*Dc];
__device__ float g_q[Bc*Sc*Dc];
__device__ float g_theta[Bc*Sc];
__device__ float g_alpha[Bc*Sc];
__device__ float g_eta[Bc*Sc];
__device__ float g_MW1[Bc*Ic*Dc];
__device__ float g_SW1[Bc*Ic*Dc];
__device__ float g_MW2[Bc*Dc*Ic];
__device__ float g_SW2[Bc*Dc*Ic];
__device__ float g_Mln[Bc*Dc];
__device__ float g_Sln[Bc*Dc];
__device__ float g_z[Bc*Cc*Ic];
__device__ float g_h[Bc*Cc*Ic];
__device__ float g_op[2*Bc*Cc*Dc];     // o partials (ksplit 2)
__device__ float g_do[Bc*Cc*Dc];
__device__ float g_gln[Bc*Cc*Dc];
__device__ float g_ppart[2*Bc*Cc*Ic];  // p partials (ksplit 2)
__device__ float g_p[Bc*Cc*Ic];
__device__ float g_nk[Bc*Cc], g_ndo[Bc*Cc], g_ngl[Bc*Cc], g_nh[Bc*Cc];
__device__ float g_sE[Bc*Cc], g_sc2[Bc*Cc];
__device__ float g_ce[Bc*Cc], g_cc[Bc*Cc];
__device__ float g_Ab[Bc], g_Bpb[Bc], g_cSb[Bc];
__device__ float g_hbuf[Bc*Sc*Ic];
__device__ float g_obuf[Bc*Sc*Dc];

__device__ __forceinline__ float sigmoidf(float v){ return 1.f/(1.f+expf(-v)); }

__device__ __forceinline__ float blockReduce(float v){
    __shared__ float sred[33];
    int lane = threadIdx.x & 31, w = threadIdx.x >> 5;
    #pragma unroll
    for(int o=16;o>0;o>>=1) v += __shfl_down_sync(0xffffffffu, v, o);
    if(lane==0) sred[w] = v;
    __syncthreads();
    int nw = (blockDim.x + 31) >> 5;
    if(w==0){
        float r = (lane < nw) ? sred[lane] : 0.f;
        #pragma unroll
        for(int o=16;o>0;o>>=1) r += __shfl_down_sync(0xffffffffu, r, o);
        if(lane==0) sred[32] = r;
    }
    __syncthreads();
    float r = sred[32];
    __syncthreads();
    return r;
}

// ---------------- init (runs every launch; deterministic) ----------------
__global__ void init_kernel(const float* __restrict__ w1, const float* __restrict__ w2,
                            const float* __restrict__ lnw){
    int idx = blockIdx.x*256 + threadIdx.x;
    float a = w1[idx], b2 = w2[idx];
    #pragma unroll
    for(int b=0;b<Bc;b++){
        g_MW1[b*Ic*Dc + idx] = a;   g_SW1[b*Ic*Dc + idx] = 0.f;
        g_MW2[b*Dc*Ic + idx] = b2;  g_SW2[b*Dc*Ic + idx] = 0.f;
    }
    if(idx < Dc){
        float l = lnw[idx];
        #pragma unroll
        for(int b=0;b<Bc;b++){ g_Mln[b*Dc+idx] = l; g_Sln[b*Dc+idx] = 0.f; }
    }
}

// ---------------- 128x128 NT tile, 256 threads, 8x8 per thread ----------------
// C[128,128] = A[128,K] @ B[128,K]^T. mode 0: store, 1: silu.
__device__ __forceinline__ void dev_gemm128(
    const float* __restrict__ Ab, int lda,
    const float* __restrict__ Bb, int ldb,
    float* __restrict__ Cb, int ldc,
    int K, int mode)
{
    __shared__ float As[16*132];
    __shared__ float Bs[16*132];
    const int tid = threadIdx.x;
    const int ty = tid>>4, tx = tid&15;
    float acc[8][8];
    #pragma unroll
    for(int i=0;i<8;i++){
        #pragma unroll
        for(int j=0;j<8;j++) acc[i][j]=0.f;
    }
    const int lf = tid*2;
    const int m0 = lf>>2,     ka0 = (lf&3)*4;
    const int m1 = (lf+1)>>2, ka1 = ((lf+1)&3)*4;
    for(int k0=0;k0<K;k0+=16){
        float4 a0 = *(const float4*)&Ab[(long long)m0*lda + k0 + ka0];
        float4 a1 = *(const float4*)&Ab[(long long)m1*lda + k0 + ka1];
        float4 b0 = *(const float4*)&Bb[(long long)m0*ldb + k0 + ka0];
        float4 b1 = *(const float4*)&Bb[(long long)m1*ldb + k0 + ka1];
        As[(ka0+0)*132+m0]=a0.x; As[(ka0+1)*132+m0]=a0.y; As[(ka0+2)*132+m0]=a0.z; As[(ka0+3)*132+m0]=a0.w;
        As[(ka1+0)*132+m1]=a1.x; As[(ka1+1)*132+m1]=a1.y; As[(ka1+2)*132+m1]=a1.z; As[(ka1+3)*132+m1]=a1.w;
        Bs[(ka0+0)*132+m0]=b0.x; Bs[(ka0+1)*132+m0]=b0.y; Bs[(ka0+2)*132+m0]=b0.z; Bs[(ka0+3)*132+m0]=b0.w;
        Bs[(ka1+0)*132+m1]=b1.x; Bs[(ka1+1)*132+m1]=b1.y; Bs[(ka1+2)*132+m1]=b1.z; Bs[(ka1+3)*132+m1]=b1.w;
        __syncthreads();
        #pragma unroll
        for(int kk=0;kk<16;kk++){
            float4 av0 = *(float4*)&As[kk*132 + ty*4];
            float4 av1 = *(float4*)&As[kk*132 + 64 + ty*4];
            float4 bv0 = *(float4*)&Bs[kk*132 + tx*4];
            float4 bv1 = *(float4*)&Bs[kk*132 + 64 + tx*4];
            float av[8] = {av0.x,av0.y,av0.z,av0.w, av1.x,av1.y,av1.z,av1.w};
            float bv[8] = {bv0.x,bv0.y,bv0.z,bv0.w, bv1.x,bv1.y,bv1.z,bv1.w};
            #pragma unroll
            for(int i=0;i<8;i++){
                #pragma unroll
                for(int j=0;j<8;j++) acc[i][j] += av[i]*bv[j];
            }
        }
        __syncthreads();
    }
    #pragma unroll
    for(int i=0;i<8;i++){
        int row = (i<4) ? (ty*4+i) : (64 + ty*4 + (i-4));
        float c[8];
        #pragma unroll
        for(int j=0;j<8;j++) c[j] = acc[i][j];
        if(mode==1){
            #pragma unroll
            for(int j=0;j<8;j++) c[j] *= sigmoidf(c[j]);
        }
        float4 c0; c0.x=c[0]; c0.y=c[1]; c0.z=c[2]; c0.w=c[3];
        float4 c1; c1.x=c[4]; c1.y=c[5]; c1.z=c[6]; c1.w=c[7];
        *(float4*)&Cb[(long long)row*ldc + tx*4] = c0;
        *(float4*)&Cb[(long long)row*ldc + 64 + tx*4] = c1;
    }
}

__global__ __launch_bounds__(256) void gemm128_gen(
    const float* __restrict__ A, long long sAz, int lda,
    const float* __restrict__ B, long long sBz, int ldb,
    float* __restrict__ C, long long sCz, int ldc,
    int K, int mode)
{
    const float* Ab = A + blockIdx.z*sAz + (long long)blockIdx.y*128*lda;
    const float* Bb = B + blockIdx.z*sBz + (long long)blockIdx.x*128*ldb;
    float* Cb = C + blockIdx.z*sCz + (long long)blockIdx.y*128*ldc + blockIdx.x*128;
    dev_gemm128(Ab, lda, Bb, ldb, Cb, ldc, K, mode);
}

__global__ __launch_bounds__(256) void gemm128_proj(
    const float* __restrict__ x, const float* __restrict__ wk,
    const float* __restrict__ wv, const float* __restrict__ wq)
{
    int w = blockIdx.z;
    const float* W = (w==0)?wk:((w==1)?wv:wq);
    float* dst = (w==0)?g_k:((w==1)?g_v:g_q);
    const float* Ab = x + (long long)blockIdx.y*128*Dc;
    const float* Bb = W + (long long)blockIdx.x*128*Dc;
    float* Cb = dst + (long long)blockIdx.y*128*Dc + blockIdx.x*128;
    dev_gemm128(Ab, Dc, Bb, Dc, Cb, Dc, Dc, 0);
}

// ---------------- 32x64 NT tile, 256 threads (split-K via blockIdx.y) ----------------
// mode 0: plain store (to partial buffer slot ks). mode 2: Z raw + silu C (no split).
__global__ __launch_bounds__(256) void nt_chunk(
    const float* __restrict__ A, long long sAz, int lda,
    const float* __restrict__ B, long long sBz, int ldb,
    float* __restrict__ C, long long sCz, int ldc, long long sKs,
    float* __restrict__ Z, long long sZz,
    int K, int mode)
{
    const int b = blockIdx.z, nt = blockIdx.x, ks = blockIdx.y;
    const long long kStart = (long long)ks*K;
    const float* Ab = A + b*sAz + kStart;
    const float* Bb = B + b*sBz + (long long)nt*64*ldb + kStart;
    float* Cb = C + (long long)ks*sKs + b*sCz + nt*64;
    __shared__ float As[32*36];
    __shared__ float Bs[32*68];
    const int tid = threadIdx.x;
    const int ty = tid>>4, tx = tid&15;
    float acc0[4]={0.f,0.f,0.f,0.f}, acc1[4]={0.f,0.f,0.f,0.f};
    const int am = tid>>3, akb = (tid&7)*4;
    const int bf0 = tid*2, bf1 = tid*2+1;
    const int bn0 = bf0>>3, bkb0 = (bf0&7)*4;
    const int bn1 = bf1>>3, bkb1 = (bf1&7)*4;
    for(int k0=0;k0<K;k0+=32){
        float4 va = *(const float4*)&Ab[(long long)am*lda + k0 + akb];
        As[(akb+0)*36+am]=va.x; As[(akb+1)*36+am]=va.y; As[(akb+2)*36+am]=va.z; As[(akb+3)*36+am]=va.w;
        float4 w0 = *(const float4*)&Bb[(long long)bn0*ldb + k0 + bkb0];
        Bs[(bkb0+0)*68+bn0]=w0.x; Bs[(bkb0+1)*68+bn0]=w0.y; Bs[(bkb0+2)*68+bn0]=w0.z; Bs[(bkb0+3)*68+bn0]=w0.w;
        float4 w1 = *(const float4*)&Bb[(long long)bn1*ldb + k0 + bkb1];
        Bs[(bkb1+0)*68+bn1]=w1.x; Bs[(bkb1+1)*68+bn1]=w1.y; Bs[(bkb1+2)*68+bn1]=w1.z; Bs[(bkb1+3)*68+bn1]=w1.w;
        __syncthreads();
        #pragma unroll
        for(int kk=0;kk<32;kk++){
            float a0 = As[kk*36 + ty];
            float a1 = As[kk*36 + 16 + ty];
            float4 bv = *(float4*)&Bs[kk*68 + tx*4];
            acc0[0]+=a0*bv.x; acc0[1]+=a0*bv.y; acc0[2]+=a0*bv.z; acc0[3]+=a0*bv.w;
            acc1[0]+=a1*bv.x; acc1[1]+=a1*bv.y; acc1[2]+=a1*bv.z; acc1[3]+=a1*bv.w;
        }
        __syncthreads();
    }
    #pragma unroll
    for(int half=0;half<2;half++){
        int row = (half==0) ? ty : (ty+16);
        float* ap = (half==0) ? acc0 : acc1;
        long long base = (long long)row*ldc + tx*4;
        if(mode==2){
            float4 z4; z4.x=ap[0]; z4.y=ap[1]; z4.z=ap[2]; z4.w=ap[3];
            *(float4*)&(Z + b*sZz + nt*64)[base] = z4;
            float4 h4;
            h4.x=ap[0]*sigmoidf(ap[0]); h4.y=ap[1]*sigmoidf(ap[1]);
            h4.z=ap[2]*sigmoidf(ap[2]); h4.w=ap[3]*sigmoidf(ap[3]);
            *(float4*)&Cb[base] = h4;
        } else {
            float4 o4; o4.x=ap[0]; o4.y=ap[1]; o4.z=ap[2]; o4.w=ap[3];
            *(float4*)&Cb[base] = o4;
        }
    }
}

// ---------------- 32x64 NN tile, 256 threads (split-K): partial = A[32,Kslice] @ B[k,n] ----------------
__global__ __launch_bounds__(256) void nn_chunk(
    const float* __restrict__ A, long long sAz, int lda,
    const float* __restrict__ B, long long sBz, int ldb,
    float* __restrict__ C, long long sCz, int ldc, long long sKs,
    int K)
{
    const int b = blockIdx.z, nt = blockIdx.x, ks = blockIdx.y;
    const long long kStart = (long long)ks*K;
    const float* Ab = A + b*sAz + kStart;
    const float* Bb = B + b*sBz + kStart*(long long)ldb + nt*64;
    float* Cb = C + (long long)ks*sKs + b*sCz + nt*64;
    __shared__ float As[32*36];
    __shared__ float Bs[32*68];
    const int tid = threadIdx.x;
    const int ty = tid>>4, tx = tid&15;
    float acc0[4]={0.f,0.f,0.f,0.f}, acc1[4]={0.f,0.f,0.f,0.f};
    const int am = tid>>3, akb = (tid&7)*4;
    const int bf0 = tid*2, bf1 = tid*2+1;
    const int bk0 = bf0>>4, bnb0 = (bf0&15)*4;
    const int bk1 = bf1>>4, bnb1 = (bf1&15)*4;
    for(int k0=0;k0<K;k0+=32){
        float4 va = *(const float4*)&Ab[(long long)am*lda + k0 + akb];
        As[(akb+0)*36+am]=va.x; As[(akb+1)*36+am]=va.y; As[(akb+2)*36+am]=va.z; As[(akb+3)*36+am]=va.w;
        float4 w0 = *(const float4*)&Bb[(long long)(k0+bk0)*ldb + bnb0];
        *(float4*)&Bs[bk0*68+bnb0] = w0;
        float4 w1 = *(const float4*)&Bb[(long long)(k0+bk1)*ldb + bnb1];
        *(float4*)&Bs[bk1*68+bnb1] = w1;
        __syncthreads();
        #pragma unroll
        for(int kk=0;kk<32;kk++){
            float a0 = As[kk*36 + ty];
            float a1 = As[kk*36 + 16 + ty];
            float4 bv = *(float4*)&Bs[kk*68 + tx*4];
            acc0[0]+=a0*bv.x; acc0[1]+=a0*bv.y; acc0[2]+=a0*bv.z; acc0[3]+=a0*bv.w;
            acc1[0]+=a1*bv.x; acc1[1]+=a1*bv.y; acc1[2]+=a1*bv.z; acc1[3]+=a1*bv.w;
        }
        __syncthreads();
    }
    #pragma unroll
    for(int half=0;half<2;half++){
        int row = (half==0) ? ty : (ty+16);
        float* ap = (half==0) ? acc0 : acc1;
        float4 o4; o4.x=ap[0]; o4.y=ap[1]; o4.z=ap[2]; o4.w=ap[3];
        *(float4*)&Cb[(long long)row*ldc + tx*4] = o4;
    }
}

// ---------------- gates ----------------
__global__ void gates_kernel(const float* __restrict__ x,
                             const float* __restrict__ thw,
                             const float* __restrict__ alw,
                             const float* __restrict__ etw){
    int row = blockIdx.x;
    const float* xr = x + (long long)row*Dc;
    float st=0.f, sa=0.f, se=0.f;
    for(int d=threadIdx.x; d<Dc; d+=128){
        float xv = xr[d];
        st += xv*thw[d]; sa += xv*alw[d]; se += xv*etw[d];
    }
    st = blockReduce(st); sa = blockReduce(sa); se = blockReduce(se);
    if(threadIdx.x == 0){
        g_theta[row] = 0.01f * sigmoidf(st);
        g_alpha[row] = sigmoidf(sa);
        g_eta[row]   = sigmoidf(se);
    }
}

// ---------------- fused activations for k, v, q ----------------
__global__ void act3_kernel(const float* __restrict__ kn, const float* __restrict__ qn){
    int which = blockIdx.x >> 11;          // 2048 rows each
    int row = blockIdx.x & 2047;
    float* buf = (which==0) ? g_k : ((which==1) ? g_v : g_q);
    long long idx = (long long)row*Dc + threadIdx.x;
    float v = buf[idx];
    float sv = v*sigmoidf(v);
    if(which==1){ buf[idx] = sv; return; }
    const float* wnorm = (which==0) ? kn : qn;
    float s2 = blockReduce(sv*sv);
    float n = rsqrtf(s2*(1.f/Dc) + 1e-6f);
    buf[idx] = sv*n*wnorm[threadIdx.x];
}

// ---------------- token backward: o-combine, rms backward, norms, scan recurrence ----------------
__global__ void token_kernel(int ci){
    int t = blockIdx.x, b = blockIdx.y, d = threadIdx.x;
    int tok = ci*Cc + t;
    long long cidx = ((long long)b*Cc + t)*Dc + d;
    float kv = g_k[((long long)b*Sc + tok)*Dc + d];
    float vv = g_v[((long long)b*Sc + tok)*Dc + d];
    float ov = g_op[cidx] + g_op[(long long)Bc*CD + cidx];
    float ln = g_Mln[b*Dc + d];
    float th = g_theta[b*Sc + tok];
    float s2 = blockReduce(ov*ov);
    float n = rsqrtf(s2*(1.f/Dc) + 1e-6f);
    float y = ln*n*ov;
    float r = kv + y - vv;
    float u = (2.f/Dc)*th*r;
    float gl = u*n*ov;
    float ws = blockReduce(u*ov*ln);
    float dov = n*ln*u - (n*n*n*ov*(1.f/Dc))*ws;
    g_do[cidx] = dov;
    g_gln[cidx] = gl;
    float hv0 = g_h[((long long)b*Cc + t)*Ic + d];
    float hv1 = g_h[((long long)b*Cc + t)*Ic + d + 512];
    float nk = blockReduce(kv*kv);
    float nd = blockReduce(dov*dov);
    float ng = blockReduce(gl*gl);
    float nh = blockReduce(hv0*hv0 + hv1*hv1);
    if(d==0){
        g_nk[b*Cc+t]=nk; g_ndo[b*Cc+t]=nd; g_ngl[b*Cc+t]=ng; g_nh[b*Cc+t]=nh;
    }
    if(t==0){
        __shared__ float sEta[32], sBeta[32];
        if(d < 32){
            sEta[d]  = g_eta[b*Sc + ci*Cc + d];
            sBeta[d] = 1.f - g_alpha[b*Sc + ci*Cc + d];
        }
        __syncthreads();
        if(d==0){
            float E=1.f, F=1.f, c=1.f, cSv=0.f;
            for(int s=Cc-1;s>=0;s--){
                g_sE[b*Cc+s] = E;
                g_sc2[b*Cc+s] = c;
                if(s==0) cSv = sEta[0]*c;
                float Fn = sBeta[s]*F;
                c = Fn + sEta[s]*c;
                E = sEta[s]*E;
                F = Fn;
            }
            g_Ab[b]=E; g_Bpb[b]=F; g_cSb[b]=cSv;
        }
    }
}

// ---------------- p-combine + dsilu + |p|^2 + clip coefs + ln update ----------------
__global__ void ln_coef_kernel(){
    int b = blockIdx.x, tid = threadIdx.x;
    __shared__ float snp[32];
    __shared__ float scf[64];
    int t = tid>>4, c0 = (tid&15)*4;
    long long rowBase = ((long long)b*Cc + t)*Ic;
    float sp = 0.f;
    #pragma unroll
    for(int j=0;j<16;j++){
        long long idx = rowBase + c0 + j*64;
        float4 pa = *(float4*)&g_ppart[idx];
        float4 pb = *(float4*)&g_ppart[(long long)Bc*CI + idx];
        float4 z4 = *(float4*)&g_z[idx];
        float4 pv;
        { float s=sigmoidf(z4.x); pv.x=(pa.x+pb.x)*(s*(1.f+z4.x*(1.f-s))); }
        { float s=sigmoidf(z4.y); pv.y=(pa.y+pb.y)*(s*(1.f+z4.y*(1.f-s))); }
        { float s=sigmoidf(z4.z); pv.z=(pa.z+pb.z)*(s*(1.f+z4.z*(1.f-s))); }
        { float s=sigmoidf(z4.w); pv.w=(pa.w+pb.w)*(s*(1.f+z4.w*(1.f-s))); }
        *(float4*)&g_p[idx] = pv;
        sp += pv.x*pv.x + pv.y*pv.y + pv.z*pv.z + pv.w*pv.w;
    }
    #pragma unroll
    for(int o=8;o>0;o>>=1) sp += __shfl_xor_sync(0xffffffffu, sp, o);
    if((tid&15)==0) snp[t] = sp;
    __syncthreads();
    if(tid < 32){
        float np = snp[tid];
        float sq = np*g_nk[b*Cc+tid] + g_ndo[b*Cc+tid]*g_nh[b*Cc+tid] + g_ngl[b*Cc+tid];
        float coef = fminf(1.f/(sqrtf(sq)+1e-6f), 1.f);
        float ce = g_sE[b*Cc+tid]*coef;
        float cc = g_sc2[b*Cc+tid]*coef;
        g_ce[b*Cc+tid]=ce; g_cc[b*Cc+tid]=cc;
        scf[tid]=ce; scf[32+tid]=cc;
    }
    __syncthreads();
    // ln state update: d = tid (512 threads = Dc)
    float S = g_Sln[b*Dc+tid], M = g_Mln[b*Dc+tid];
    float se_=0.f, sc_=0.f;
    #pragma unroll
    for(int t2=0;t2<Cc;t2++){
        float g = g_gln[((long long)b*Cc + t2)*Dc + tid];
        se_ += scf[t2]*g;
        sc_ += scf[32+t2]*g;
    }
    g_Sln[b*Dc+tid] = g_Ab[b]*S - se_;
    g_Mln[b*Dc+tid] = g_Bpb[b]*M + g_cSb[b]*S - sc_;
}

// ---------------- both rank-32 state updates in one launch ----------------
__global__ __launch_bounds__(256) void rank_both(int ci){
    int zz = blockIdx.z;
    int b = zz & 3, which = zz >> 2;
    float *Sm, *Mm; const float *P, *Kv;
    int ldS, pStr, kStr;
    if(which==0){
        int rt = blockIdx.y, ct = blockIdx.x;      // 16 x 8
        Sm = g_SW1 + (long long)b*ID + (long long)rt*64*Dc + ct*64;
        Mm = g_MW1 + (long long)b*ID + (long long)rt*64*Dc + ct*64;
        ldS = Dc;
        P = g_p + (long long)b*CI + rt*64;  pStr = Ic;
        Kv = g_k + ((long long)b*Sc + ci*Cc)*Dc + ct*64;  kStr = Dc;
    } else {
        int rt = blockIdx.x, ct = blockIdx.y;      // 8 x 16
        Sm = g_SW2 + (long long)b*ID + (long long)rt*64*Ic + ct*64;
        Mm = g_MW2 + (long long)b*ID + (long long)rt*64*Ic + ct*64;
        ldS = Ic;
        P = g_do + (long long)b*CD + rt*64;  pStr = Dc;
        Kv = g_h + (long long)b*CI + ct*64;  kStr = Ic;
    }
    __shared__ float Ps[32*68];
    __shared__ float Ks[32*68];
    __shared__ float sce[32], scc[32];
    const int tid = threadIdx.x;
    #pragma unroll
    for(int i=0;i<2;i++){
        int f = tid*2 + i;
        int tt = f>>4, cb = (f&15)*4;
        *(float4*)&Ps[tt*68+cb] = *(const float4*)&P[(long long)tt*pStr + cb];
        *(float4*)&Ks[tt*68+cb] = *(const float4*)&Kv[(long long)tt*kStr + cb];
    }
    if(tid < 32){ sce[tid] = g_ce[b*Cc+tid]; scc[tid] = g_cc[b*Cc+tid]; }
    __syncthreads();
    const int ty = tid>>4, tx = tid&15;   // rows ty*4..+3, cols tx*4..+3
    float ae[4][4], ac[4][4];
    #pragma unroll
    for(int i=0;i<4;i++){
        #pragma unroll
        for(int j=0;j<4;j++){ ae[i][j]=0.f; ac[i][j]=0.f; }
    }
    #pragma unroll
    for(int t=0;t<32;t++){
        float ce = sce[t], cc = scc[t];
        float4 pv = *(float4*)&Ps[t*68 + ty*4];
        float4 k4 = *(float4*)&Ks[t*68 + tx*4];
        float p4[4] = {pv.x, pv.y, pv.z, pv.w};
        float kk4[4] = {k4.x, k4.y, k4.z, k4.w};
        #pragma unroll
        for(int i=0;i<4;i++){
            float pe = ce*p4[i], pc = cc*p4[i];
            #pragma unroll
            for(int j=0;j<4;j++){
                ae[i][j] += pe*kk4[j];
                ac[i][j] += pc*kk4[j];
            }
        }
    }
    float A = g_Ab[b], Bp = g_Bpb[b], cS = g_cSb[b];
    #pragma unroll
    for(int i=0;i<4;i++){
        long long base = (long long)(ty*4+i)*ldS + tx*4;
        float4 s4 = *(float4*)&Sm[base];
        float4 m4 = *(float4*)&Mm[base];
        float4 ns, nm;
        ns.x = A*s4.x - ae[i][0]; nm.x = Bp*m4.x + cS*s4.x - ac[i][0];
        ns.y = A*s4.y - ae[i][1]; nm.y = Bp*m4.y + cS*s4.y - ac[i][1];
        ns.z = A*s4.z - ae[i][2]; nm.z = Bp*m4.z + cS*s4.z - ac[i][2];
        ns.w = A*s4.w - ae[i][3]; nm.w = Bp*m4.w + cS*s4.w - ac[i][3];
        *(float4*)&Sm[base] = ns;
        *(float4*)&Mm[base] = nm;
    }
}

// ---------------- final combine ----------------
__global__ void final_kernel(float* __restrict__ out){
    int row = blockIdx.x, d = threadIdx.x;
    int b = row >> 9;
    long long idx = (long long)row*Dc + d;
    float qv = g_q[idx];
    float ov = g_obuf[idx];
    float ln = g_Mln[b*Dc + d];
    float s2 = blockReduce(ov*ov);
    float n = rsqrtf(s2*(1.f/Dc) + 1e-6f);
    out[idx] = qv + ov*n*ln;
}

extern "C" void kernel_launch(void* const* d_in, const int* in_sizes, int n_in,
                              void* d_out, int out_size){
    const float* x   = (const float*)d_in[0];
    const float* wq  = (const float*)d_in[1];
    const float* wk  = (const float*)d_in[2];
    const float* wv  = (const float*)d_in[3];
    const float* qn  = (const float*)d_in[4];
    const float* kn  = (const float*)d_in[5];
    const float* alw = (const float*)d_in[6];
    const float* thw = (const float*)d_in[7];
    const float* etw = (const float*)d_in[8];
    const float* w1  = (const float*)d_in[9];
    const float* w2  = (const float*)d_in[10];
    const float* lnw = (const float*)d_in[11];
    float* out = (float*)d_out;

    float *k_, *h_, *z_, *op_, *do_, *pp_, *mw1_, *mw2_, *q_, *hbuf_, *obuf_;
    cudaGetSymbolAddress((void**)&k_, g_k);
    cudaGetSymbolAddress((void**)&h_, g_h);
    cudaGetSymbolAddress((void**)&z_, g_z);
    cudaGetSymbolAddress((void**)&op_, g_op);
    cudaGetSymbolAddress((void**)&do_, g_do);
    cudaGetSymbolAddress((void**)&pp_, g_ppart);
    cudaGetSymbolAddress((void**)&mw1_, g_MW1);
    cudaGetSymbolAddress((void**)&mw2_, g_MW2);
    cudaGetSymbolAddress((void**)&q_, g_q);
    cudaGetSymbolAddress((void**)&hbuf_, g_hbuf);
    cudaGetSymbolAddress((void**)&obuf_, g_obuf);

    init_kernel<<<ID/256, 256>>>(w1, w2, lnw);

    // all three projections in one launch: grid (ntile=4, mtile=16, w=3)
    gemm128_proj<<<dim3(4, 16, 3), 256>>>(x, wk, wv, wq);
    gates_kernel<<<Bc*Sc, 128>>>(x, thw, alw, etw);
    act3_kernel<<<3*Bc*Sc, Dc>>>(kn, qn);

    for(int ci=0; ci<NCc; ci++){
        // PA: z/h = silu(Kc @ MW1^T): grid (16 ntiles, 1, 4b), K=512
        nt_chunk<<<dim3(16,1,4), 256>>>(k_ + (long long)ci*Cc*Dc, SD, Dc,
                                        mw1_, ID, Dc,
                                        h_, CI, Ic, 0,
                                        z_, CI, 512, 2);
        // PB: o partials = H @ MW2^T: grid (8 ntiles, 2 ksplit, 4b), K=512/block
        nt_chunk<<<dim3(8,2,4), 256>>>(h_, CI, Ic,
                                       mw2_, ID, Ic,
                                       op_, CD, Dc, (long long)Bc*CD,
                                       nullptr, 0, 512, 0);
        // token backward (+norms +scan recurrence)
        token_kernel<<<dim3(Cc, Bc), Dc>>>(ci);
        // PD: p partials = DO @ MW2 (NN): grid (16 ntiles, 2 ksplit, 4b), K=256/block
        nn_chunk<<<dim3(16,2,4), 256>>>(do_, CD, Dc,
                                        mw2_, ID, Ic,
                                        pp_, CI, Ic, (long long)Bc*CI,
                                        256);
        // p combine + dsilu + |p|^2 + clip coefs + ln update
        ln_coef_kernel<<<Bc, Dc>>>();
        // rank-32 updates for W1 and W2 states
        rank_both<<<dim3(8, 16, 8), 256>>>(ci);
    }

    // retrieval: h = silu(q @ MW1^T), o = h @ MW2^T
    gemm128_gen<<<dim3(8, 4, 4), 256>>>(q_, SD, Dc, mw1_, ID, Dc, hbuf_, SI, Ic, 512, 1);
    gemm128_gen<<<dim3(4, 4, 4), 256>>>(hbuf_, SI, Ic, mw2_, ID, Ic, obuf_, SD, Dc, 1024, 0);
    final_kernel<<<Bc*Sc, Dc>>>(out);
}

// round 8
// speedup vs baseline: 1.7586x; 1.1689x over previous
#include <cuda_runtime.h>
#include <math.h>

constexpr int Bc=4, Sc=512, Dc=512, Ic=1024, Cc=32, NCc=16;
constexpr long long SD=(long long)Sc*Dc;
constexpr long long ID=(long long)Ic*Dc;
constexpr long long CI=(long long)Cc*Ic;
constexpr long long CD=(long long)Cc*Dc;
constexpr long long SI=(long long)Sc*Ic;

// ---------------- persistent device scratch ----------------
__device__ float g_k[Bc*Sc*Dc];
__device__ float g_v[Bc*Sc*Dc];
__device__ float g_q[Bc*Sc*Dc];
__device__ float g_theta[Bc*Sc];
__device__ float g_alpha[Bc*Sc];
__device__ float g_eta[Bc*Sc];
__device__ float g_MW1[Bc*Ic*Dc];
__device__ float g_SW1[Bc*Ic*Dc];
__device__ float g_MW2[Bc*Dc*Ic];
__device__ float g_SW2[Bc*Dc*Ic];
__device__ float g_Mln[Bc*Dc];
__device__ float g_Sln[Bc*Dc];
__device__ float g_z[Bc*Cc*Ic];
__device__ float g_h[Bc*Cc*Ic];
__device__ float g_op[2*Bc*Cc*Dc];     // o partials (ksplit 2)
__device__ float g_do[Bc*Cc*Dc];
__device__ float g_gln[Bc*Cc*Dc];
__device__ float g_p[Bc*Cc*Ic];
__device__ float g_npp[Bc*Cc*32];      // |p|^2 partials per 32-col tile
__device__ float g_nk[Bc*Cc], g_ndo[Bc*Cc], g_ngl[Bc*Cc], g_nh[Bc*Cc];
__device__ float g_sE[Bc*Cc], g_sc2[Bc*Cc];
__device__ float g_Ab[Bc], g_Bpb[Bc], g_cSb[Bc];
__device__ float g_hbuf[Bc*Sc*Ic];
__device__ float g_obuf[Bc*Sc*Dc];

__device__ __forceinline__ float sigmoidf(float v){ return 1.f/(1.f+expf(-v)); }

__device__ __forceinline__ float blockReduce(float v){
    __shared__ float sred[33];
    int lane = threadIdx.x & 31, w = threadIdx.x >> 5;
    #pragma unroll
    for(int o=16;o>0;o>>=1) v += __shfl_down_sync(0xffffffffu, v, o);
    if(lane==0) sred[w] = v;
    __syncthreads();
    int nw = (blockDim.x + 31) >> 5;
    if(w==0){
        float r = (lane < nw) ? sred[lane] : 0.f;
        #pragma unroll
        for(int o=16;o>0;o>>=1) r += __shfl_down_sync(0xffffffffu, r, o);
        if(lane==0) sred[32] = r;
    }
    __syncthreads();
    float r = sred[32];
    __syncthreads();
    return r;
}

// ---------------- init ----------------
__global__ void init_kernel(const float* __restrict__ w1, const float* __restrict__ w2,
                            const float* __restrict__ lnw){
    int idx = blockIdx.x*256 + threadIdx.x;
    float a = w1[idx], b2 = w2[idx];
    #pragma unroll
    for(int b=0;b<Bc;b++){
        g_MW1[b*Ic*Dc + idx] = a;   g_SW1[b*Ic*Dc + idx] = 0.f;
        g_MW2[b*Dc*Ic + idx] = b2;  g_SW2[b*Dc*Ic + idx] = 0.f;
    }
    if(idx < Dc){
        float l = lnw[idx];
        #pragma unroll
        for(int b=0;b<Bc;b++){ g_Mln[b*Dc+idx] = l; g_Sln[b*Dc+idx] = 0.f; }
    }
}

// ---------------- 128x128 NT tile, 256 threads, 8x8 per thread ----------------
__device__ __forceinline__ void dev_gemm128(
    const float* __restrict__ Ab, int lda,
    const float* __restrict__ Bb, int ldb,
    float* __restrict__ Cb, int ldc,
    int K, int mode)
{
    __shared__ float As[16*132];
    __shared__ float Bs[16*132];
    const int tid = threadIdx.x;
    const int ty = tid>>4, tx = tid&15;
    float acc[8][8];
    #pragma unroll
    for(int i=0;i<8;i++){
        #pragma unroll
        for(int j=0;j<8;j++) acc[i][j]=0.f;
    }
    const int lf = tid*2;
    const int m0 = lf>>2,     ka0 = (lf&3)*4;
    const int m1 = (lf+1)>>2, ka1 = ((lf+1)&3)*4;
    for(int k0=0;k0<K;k0+=16){
        float4 a0 = *(const float4*)&Ab[(long long)m0*lda + k0 + ka0];
        float4 a1 = *(const float4*)&Ab[(long long)m1*lda + k0 + ka1];
        float4 b0 = *(const float4*)&Bb[(long long)m0*ldb + k0 + ka0];
        float4 b1 = *(const float4*)&Bb[(long long)m1*ldb + k0 + ka1];
        As[(ka0+0)*132+m0]=a0.x; As[(ka0+1)*132+m0]=a0.y; As[(ka0+2)*132+m0]=a0.z; As[(ka0+3)*132+m0]=a0.w;
        As[(ka1+0)*132+m1]=a1.x; As[(ka1+1)*132+m1]=a1.y; As[(ka1+2)*132+m1]=a1.z; As[(ka1+3)*132+m1]=a1.w;
        Bs[(ka0+0)*132+m0]=b0.x; Bs[(ka0+1)*132+m0]=b0.y; Bs[(ka0+2)*132+m0]=b0.z; Bs[(ka0+3)*132+m0]=b0.w;
        Bs[(ka1+0)*132+m1]=b1.x; Bs[(ka1+1)*132+m1]=b1.y; Bs[(ka1+2)*132+m1]=b1.z; Bs[(ka1+3)*132+m1]=b1.w;
        __syncthreads();
        #pragma unroll
        for(int kk=0;kk<16;kk++){
            float4 av0 = *(float4*)&As[kk*132 + ty*4];
            float4 av1 = *(float4*)&As[kk*132 + 64 + ty*4];
            float4 bv0 = *(float4*)&Bs[kk*132 + tx*4];
            float4 bv1 = *(float4*)&Bs[kk*132 + 64 + tx*4];
            float av[8] = {av0.x,av0.y,av0.z,av0.w, av1.x,av1.y,av1.z,av1.w};
            float bv[8] = {bv0.x,bv0.y,bv0.z,bv0.w, bv1.x,bv1.y,bv1.z,bv1.w};
            #pragma unroll
            for(int i=0;i<8;i++){
                #pragma unroll
                for(int j=0;j<8;j++) acc[i][j] += av[i]*bv[j];
            }
        }
        __syncthreads();
    }
    #pragma unroll
    for(int i=0;i<8;i++){
        int row = (i<4) ? (ty*4+i) : (64 + ty*4 + (i-4));
        float c[8];
        #pragma unroll
        for(int j=0;j<8;j++) c[j] = acc[i][j];
        if(mode==1){
            #pragma unroll
            for(int j=0;j<8;j++) c[j] *= sigmoidf(c[j]);
        }
        float4 c0; c0.x=c[0]; c0.y=c[1]; c0.z=c[2]; c0.w=c[3];
        float4 c1; c1.x=c[4]; c1.y=c[5]; c1.z=c[6]; c1.w=c[7];
        *(float4*)&Cb[(long long)row*ldc + tx*4] = c0;
        *(float4*)&Cb[(long long)row*ldc + 64 + tx*4] = c1;
    }
}

__global__ __launch_bounds__(256) void gemm128_gen(
    const float* __restrict__ A, long long sAz, int lda,
    const float* __restrict__ B, long long sBz, int ldb,
    float* __restrict__ C, long long sCz, int ldc,
    int K, int mode)
{
    const float* Ab = A + blockIdx.z*sAz + (long long)blockIdx.y*128*lda;
    const float* Bb = B + blockIdx.z*sBz + (long long)blockIdx.x*128*ldb;
    float* Cb = C + blockIdx.z*sCz + (long long)blockIdx.y*128*ldc + blockIdx.x*128;
    dev_gemm128(Ab, lda, Bb, ldb, Cb, ldc, K, mode);
}

__global__ __launch_bounds__(256) void gemm128_proj(
    const float* __restrict__ x, const float* __restrict__ wk,
    const float* __restrict__ wv, const float* __restrict__ wq)
{
    int w = blockIdx.z;
    const float* W = (w==0)?wk:((w==1)?wv:wq);
    float* dst = (w==0)?g_k:((w==1)?g_v:g_q);
    const float* Ab = x + (long long)blockIdx.y*128*Dc;
    const float* Bb = W + (long long)blockIdx.x*128*Dc;
    float* Cb = dst + (long long)blockIdx.y*128*Dc + blockIdx.x*128;
    dev_gemm128(Ab, Dc, Bb, Dc, Cb, Dc, Dc, 0);
}

// ================= chunk GEMMs: 32x32 tiles, double-buffered =================
// PA: z/h = silu(Kc @ MW1^T). grid (32 nt, 1, 4 b). K = 512 (16 k-tiles).
__global__ __launch_bounds__(256) void pa_kernel(int ci){
    const int b = blockIdx.z, nt = blockIdx.x;
    const float* A = g_k + ((long long)b*Sc + ci*Cc)*Dc;       // [32, 512], ld=Dc
    const float* B = g_MW1 + (long long)b*ID + (long long)nt*32*Dc; // [32, 512], ld=Dc
    __shared__ float As[2][1152];
    __shared__ float Bs[2][1152];
    const int tid = threadIdx.x;
    const int lm = tid>>3, lk = (tid&7)*4;
    const int r = tid>>3, cb = (tid&7)*4;
    float4 aN = *(const float4*)&A[(long long)lm*Dc + lk];
    float4 bN = *(const float4*)&B[(long long)lm*Dc + lk];
    float acc[4]={0.f,0.f,0.f,0.f};
    for(int kt=0;kt<16;kt++){
        int cur = kt&1;
        As[cur][(lk+0)*36+lm]=aN.x; As[cur][(lk+1)*36+lm]=aN.y;
        As[cur][(lk+2)*36+lm]=aN.z; As[cur][(lk+3)*36+lm]=aN.w;
        Bs[cur][(lk+0)*36+lm]=bN.x; Bs[cur][(lk+1)*36+lm]=bN.y;
        Bs[cur][(lk+2)*36+lm]=bN.z; Bs[cur][(lk+3)*36+lm]=bN.w;
        __syncthreads();
        if(kt<15){
            int k0 = (kt+1)*32;
            aN = *(const float4*)&A[(long long)lm*Dc + k0 + lk];
            bN = *(const float4*)&B[(long long)lm*Dc + k0 + lk];
        }
        #pragma unroll
        for(int kk=0;kk<32;kk++){
            float a = As[cur][kk*36+r];
            float4 b4 = *(float4*)&Bs[cur][kk*36+cb];
            acc[0]+=a*b4.x; acc[1]+=a*b4.y; acc[2]+=a*b4.z; acc[3]+=a*b4.w;
        }
    }
    long long idx = (long long)b*CI + (long long)r*Ic + nt*32 + cb;
    float4 z4; z4.x=acc[0]; z4.y=acc[1]; z4.z=acc[2]; z4.w=acc[3];
    *(float4*)&g_z[idx] = z4;
    float4 h4;
    h4.x=acc[0]*sigmoidf(acc[0]); h4.y=acc[1]*sigmoidf(acc[1]);
    h4.z=acc[2]*sigmoidf(acc[2]); h4.w=acc[3]*sigmoidf(acc[3]);
    *(float4*)&g_h[idx] = h4;
}

// PB: o partials = H @ MW2^T. grid (16 nt, 2 ks, 4 b). K=512 per block.
__global__ __launch_bounds__(256) void pb_kernel(){
    const int b = blockIdx.z, nt = blockIdx.x, ks = blockIdx.y;
    const float* A = g_h + (long long)b*CI + ks*512;                          // ld=Ic
    const float* B = g_MW2 + (long long)b*ID + (long long)nt*32*Ic + ks*512;  // ld=Ic
    __shared__ float As[2][1152];
    __shared__ float Bs[2][1152];
    const int tid = threadIdx.x;
    const int lm = tid>>3, lk = (tid&7)*4;
    const int r = tid>>3, cb = (tid&7)*4;
    float4 aN = *(const float4*)&A[(long long)lm*Ic + lk];
    float4 bN = *(const float4*)&B[(long long)lm*Ic + lk];
    float acc[4]={0.f,0.f,0.f,0.f};
    for(int kt=0;kt<16;kt++){
        int cur = kt&1;
        As[cur][(lk+0)*36+lm]=aN.x; As[cur][(lk+1)*36+lm]=aN.y;
        As[cur][(lk+2)*36+lm]=aN.z; As[cur][(lk+3)*36+lm]=aN.w;
        Bs[cur][(lk+0)*36+lm]=bN.x; Bs[cur][(lk+1)*36+lm]=bN.y;
        Bs[cur][(lk+2)*36+lm]=bN.z; Bs[cur][(lk+3)*36+lm]=bN.w;
        __syncthreads();
        if(kt<15){
            int k0 = (kt+1)*32;
            aN = *(const float4*)&A[(long long)lm*Ic + k0 + lk];
            bN = *(const float4*)&B[(long long)lm*Ic + k0 + lk];
        }
        #pragma unroll
        for(int kk=0;kk<32;kk++){
            float a = As[cur][kk*36+r];
            float4 b4 = *(float4*)&Bs[cur][kk*36+cb];
            acc[0]+=a*b4.x; acc[1]+=a*b4.y; acc[2]+=a*b4.z; acc[3]+=a*b4.w;
        }
    }
    float* Cb = g_op + (long long)ks*(Bc*CD) + (long long)b*CD + nt*32;
    float4 o4; o4.x=acc[0]; o4.y=acc[1]; o4.z=acc[2]; o4.w=acc[3];
    *(float4*)&Cb[(long long)r*Dc + cb] = o4;
}

// PD: p = (DO @ MW2) * dsilu(z) + |p|^2 tile partials. grid (32 nt, 1, 4 b). K=512.
__global__ __launch_bounds__(256) void pd_kernel(){
    const int b = blockIdx.z, nt = blockIdx.x;
    const float* A = g_do + (long long)b*CD;                 // [32, 512], ld=Dc
    const float* B = g_MW2 + (long long)b*ID + nt*32;        // B[k][n], ld=Ic
    __shared__ float As[2][1152];
    __shared__ float Bs[2][1152];
    const int tid = threadIdx.x;
    const int lm = tid>>3, lk = (tid&7)*4;        // A loader
    const int bk = tid>>3, bnb = (tid&7)*4;       // B loader (row=k, col=n)
    const int r = tid>>3, cb = (tid&7)*4;
    float4 aN = *(const float4*)&A[(long long)lm*Dc + lk];
    float4 bN = *(const float4*)&B[(long long)bk*Ic + bnb];
    float acc[4]={0.f,0.f,0.f,0.f};
    for(int kt=0;kt<16;kt++){
        int cur = kt&1;
        As[cur][(lk+0)*36+lm]=aN.x; As[cur][(lk+1)*36+lm]=aN.y;
        As[cur][(lk+2)*36+lm]=aN.z; As[cur][(lk+3)*36+lm]=aN.w;
        *(float4*)&Bs[cur][bk*36+bnb] = bN;
        __syncthreads();
        if(kt<15){
            int k0 = (kt+1)*32;
            aN = *(const float4*)&A[(long long)lm*Dc + k0 + lk];
            bN = *(const float4*)&B[(long long)(k0+bk)*Ic + bnb];
        }
        #pragma unroll
        for(int kk=0;kk<32;kk++){
            float a = As[cur][kk*36+r];
            float4 b4 = *(float4*)&Bs[cur][kk*36+cb];
            acc[0]+=a*b4.x; acc[1]+=a*b4.y; acc[2]+=a*b4.z; acc[3]+=a*b4.w;
        }
    }
    long long idx = (long long)b*CI + (long long)r*Ic + nt*32 + cb;
    float4 z4 = *(const float4*)&g_z[idx];
    float4 pv;
    { float s=sigmoidf(z4.x); pv.x=acc[0]*(s*(1.f+z4.x*(1.f-s))); }
    { float s=sigmoidf(z4.y); pv.y=acc[1]*(s*(1.f+z4.y*(1.f-s))); }
    { float s=sigmoidf(z4.z); pv.z=acc[2]*(s*(1.f+z4.z*(1.f-s))); }
    { float s=sigmoidf(z4.w); pv.w=acc[3]*(s*(1.f+z4.w*(1.f-s))); }
    *(float4*)&g_p[idx] = pv;
    float sp = pv.x*pv.x + pv.y*pv.y + pv.z*pv.z + pv.w*pv.w;
    sp += __shfl_xor_sync(0xffffffffu, sp, 1);
    sp += __shfl_xor_sync(0xffffffffu, sp, 2);
    sp += __shfl_xor_sync(0xffffffffu, sp, 4);
    if((tid&7)==0) g_npp[(b*Cc+r)*32 + nt] = sp;
}

// ---------------- gates ----------------
__global__ void gates_kernel(const float* __restrict__ x,
                             const float* __restrict__ thw,
                             const float* __restrict__ alw,
                             const float* __restrict__ etw){
    int row = blockIdx.x;
    const float* xr = x + (long long)row*Dc;
    float st=0.f, sa=0.f, se=0.f;
    for(int d=threadIdx.x; d<Dc; d+=128){
        float xv = xr[d];
        st += xv*thw[d]; sa += xv*alw[d]; se += xv*etw[d];
    }
    st = blockReduce(st); sa = blockReduce(sa); se = blockReduce(se);
    if(threadIdx.x == 0){
        g_theta[row] = 0.01f * sigmoidf(st);
        g_alpha[row] = sigmoidf(sa);
        g_eta[row]   = sigmoidf(se);
    }
}

// ---------------- fused activations for k, v, q ----------------
__global__ void act3_kernel(const float* __restrict__ kn, const float* __restrict__ qn){
    int which = blockIdx.x >> 11;
    int row = blockIdx.x & 2047;
    float* buf = (which==0) ? g_k : ((which==1) ? g_v : g_q);
    long long idx = (long long)row*Dc + threadIdx.x;
    float v = buf[idx];
    float sv = v*sigmoidf(v);
    if(which==1){ buf[idx] = sv; return; }
    const float* wnorm = (which==0) ? kn : qn;
    float s2 = blockReduce(sv*sv);
    float n = rsqrtf(s2*(1.f/Dc) + 1e-6f);
    buf[idx] = sv*n*wnorm[threadIdx.x];
}

// ---------------- token backward ----------------
__global__ void token_kernel(int ci){
    int t = blockIdx.x, b = blockIdx.y, d = threadIdx.x;
    int tok = ci*Cc + t;
    long long cidx = ((long long)b*Cc + t)*Dc + d;
    float kv = g_k[((long long)b*Sc + tok)*Dc + d];
    float vv = g_v[((long long)b*Sc + tok)*Dc + d];
    float ov = g_op[cidx] + g_op[(long long)Bc*CD + cidx];
    float ln = g_Mln[b*Dc + d];
    float th = g_theta[b*Sc + tok];
    float s2 = blockReduce(ov*ov);
    float n = rsqrtf(s2*(1.f/Dc) + 1e-6f);
    float y = ln*n*ov;
    float r = kv + y - vv;
    float u = (2.f/Dc)*th*r;
    float gl = u*n*ov;
    float ws = blockReduce(u*ov*ln);
    float dov = n*ln*u - (n*n*n*ov*(1.f/Dc))*ws;
    g_do[cidx] = dov;
    g_gln[cidx] = gl;
    float hv0 = g_h[((long long)b*Cc + t)*Ic + d];
    float hv1 = g_h[((long long)b*Cc + t)*Ic + d + 512];
    float nk = blockReduce(kv*kv);
    float nd = blockReduce(dov*dov);
    float ng = blockReduce(gl*gl);
    float nh = blockReduce(hv0*hv0 + hv1*hv1);
    if(d==0){
        g_nk[b*Cc+t]=nk; g_ndo[b*Cc+t]=nd; g_ngl[b*Cc+t]=ng; g_nh[b*Cc+t]=nh;
    }
    if(t==0){
        __shared__ float sEta[32], sBeta[32];
        if(d < 32){
            sEta[d]  = g_eta[b*Sc + ci*Cc + d];
            sBeta[d] = 1.f - g_alpha[b*Sc + ci*Cc + d];
        }
        __syncthreads();
        if(d==0){
            float E=1.f, F=1.f, c=1.f, cSv=0.f;
            for(int s=Cc-1;s>=0;s--){
                g_sE[b*Cc+s] = E;
                g_sc2[b*Cc+s] = c;
                if(s==0) cSv = sEta[0]*c;
                float Fn = sBeta[s]*F;
                c = Fn + sEta[s]*c;
                E = sEta[s]*E;
                F = Fn;
            }
            g_Ab[b]=E; g_Bpb[b]=F; g_cSb[b]=cSv;
        }
    }
}

// ================= rank updates (64x128 tiles) + ln update, one launch =================
// grid: 516 blocks. 0..255 -> W1, 256..511 -> W2, 512..515 -> ln.
__global__ void __launch_bounds__(256, 2) rank_ln_kernel(int ci){
    const int bid = blockIdx.x, tid = threadIdx.x;
    __shared__ float Ps[32*68];
    __shared__ float Ks[32*132];
    __shared__ float sce[32], scc[32];

    int b;
    const float *P = nullptr, *Kv = nullptr;
    float *Sm = nullptr, *Mm = nullptr;
    int ld = 0, pStr = 0, kStr = 0;
    bool isLn = false;
    if(bid < 256){
        int u = bid; b = u>>6; int tile = u&63;
        int rt = tile>>2, ct = tile&3;
        Sm = g_SW1 + (long long)b*ID + (long long)rt*64*Dc + ct*128;
        Mm = g_MW1 + (long long)b*ID + (long long)rt*64*Dc + ct*128;
        ld = Dc;
        P  = g_p + (long long)b*CI + rt*64;   pStr = Ic;
        Kv = g_k + ((long long)b*Sc + ci*Cc)*Dc + ct*128;  kStr = Dc;
    } else if(bid < 512){
        int u = bid-256; b = u>>6; int tile = u&63;
        int rt = tile>>3, ct = tile&7;
        Sm = g_SW2 + (long long)b*ID + (long long)rt*64*Ic + ct*128;
        Mm = g_MW2 + (long long)b*ID + (long long)rt*64*Ic + ct*128;
        ld = Ic;
        P  = g_do + (long long)b*CD + rt*64;  pStr = Dc;
        Kv = g_h + (long long)b*CI + ct*128;  kStr = Ic;
    } else {
        isLn = true; b = bid-512;
    }

    // clip coefficients (computed redundantly per block; cheap)
    if(tid < 32){
        float np = 0.f;
        #pragma unroll
        for(int j=0;j<32;j++) np += g_npp[(b*Cc+tid)*32 + j];
        float sq = np*g_nk[b*Cc+tid] + g_ndo[b*Cc+tid]*g_nh[b*Cc+tid] + g_ngl[b*Cc+tid];
        float coef = fminf(1.f/(sqrtf(sq)+1e-6f), 1.f);
        sce[tid] = g_sE[b*Cc+tid]*coef;
        scc[tid] = g_sc2[b*Cc+tid]*coef;
    }

    if(isLn){
        __syncthreads();
        float A = g_Ab[b], Bp = g_Bpb[b], cS = g_cSb[b];
        #pragma unroll
        for(int rep=0;rep<2;rep++){
            int d = tid + rep*256;
            float S = g_Sln[b*Dc+d], M = g_Mln[b*Dc+d];
            float se_=0.f, sc_=0.f;
            #pragma unroll
            for(int t2=0;t2<Cc;t2++){
                float g = g_gln[((long long)b*Cc + t2)*Dc + d];
                se_ += sce[t2]*g;
                sc_ += scc[t2]*g;
            }
            g_Sln[b*Dc+d] = A*S - se_;
            g_Mln[b*Dc+d] = Bp*M + cS*S - sc_;
        }
        return;
    }

    // load P (32x64) and K (32x128)
    #pragma unroll
    for(int i=0;i<2;i++){
        int f = tid*2 + i;
        int tt = f>>4, cb = (f&15)*4;
        *(float4*)&Ps[tt*68+cb] = *(const float4*)&P[(long long)tt*pStr + cb];
    }
    #pragma unroll
    for(int i=0;i<4;i++){
        int f = tid*4 + i;
        int tt = f>>5, cb = (f&31)*4;
        *(float4*)&Ks[tt*132+cb] = *(const float4*)&Kv[(long long)tt*kStr + cb];
    }
    __syncthreads();

    const int ty = tid>>4, tx = tid&15;   // rows ty*4..+3 (of 64), cols tx*8..+7 (of 128)
    float ae[4][8], ac[4][8];
    #pragma unroll
    for(int i=0;i<4;i++){
        #pragma unroll
        for(int j=0;j<8;j++){ ae[i][j]=0.f; ac[i][j]=0.f; }
    }
    #pragma unroll
    for(int t=0;t<32;t++){
        float ce = sce[t], cc = scc[t];
        float4 p4 = *(float4*)&Ps[t*68 + ty*4];
        float4 ka = *(float4*)&Ks[t*132 + tx*8];
        float4 kb = *(float4*)&Ks[t*132 + tx*8 + 4];
        float pv[4] = {p4.x, p4.y, p4.z, p4.w};
        float kv8[8] = {ka.x,ka.y,ka.z,ka.w, kb.x,kb.y,kb.z,kb.w};
        #pragma unroll
        for(int i=0;i<4;i++){
            float pe = ce*pv[i], pc = cc*pv[i];
            #pragma unroll
            for(int j=0;j<8;j++){
                ae[i][j] += pe*kv8[j];
                ac[i][j] += pc*kv8[j];
            }
        }
    }
    float A = g_Ab[b], Bp = g_Bpb[b], cS = g_cSb[b];
    #pragma unroll
    for(int i=0;i<4;i++){
        long long base = (long long)(ty*4+i)*ld + tx*8;
        #pragma unroll
        for(int half=0;half<2;half++){
            float4 s4 = *(float4*)&Sm[base + half*4];
            float4 m4 = *(float4*)&Mm[base + half*4];
            float4 ns, nm;
            int j0 = half*4;
            ns.x = A*s4.x - ae[i][j0+0]; nm.x = Bp*m4.x + cS*s4.x - ac[i][j0+0];
            ns.y = A*s4.y - ae[i][j0+1]; nm.y = Bp*m4.y + cS*s4.y - ac[i][j0+1];
            ns.z = A*s4.z - ae[i][j0+2]; nm.z = Bp*m4.z + cS*s4.z - ac[i][j0+2];
            ns.w = A*s4.w - ae[i][j0+3]; nm.w = Bp*m4.w + cS*s4.w - ac[i][j0+3];
            *(float4*)&Sm[base + half*4] = ns;
            *(float4*)&Mm[base + half*4] = nm;
        }
    }
}

// ---------------- final combine ----------------
__global__ void final_kernel(float* __restrict__ out){
    int row = blockIdx.x, d = threadIdx.x;
    int b = row >> 9;
    long long idx = (long long)row*Dc + d;
    float qv = g_q[idx];
    float ov = g_obuf[idx];
    float ln = g_Mln[b*Dc + d];
    float s2 = blockReduce(ov*ov);
    float n = rsqrtf(s2*(1.f/Dc) + 1e-6f);
    out[idx] = qv + ov*n*ln;
}

extern "C" void kernel_launch(void* const* d_in, const int* in_sizes, int n_in,
                              void* d_out, int out_size){
    const float* x   = (const float*)d_in[0];
    const float* wq  = (const float*)d_in[1];
    const float* wk  = (const float*)d_in[2];
    const float* wv  = (const float*)d_in[3];
    const float* qn  = (const float*)d_in[4];
    const float* kn  = (const float*)d_in[5];
    const float* alw = (const float*)d_in[6];
    const float* thw = (const float*)d_in[7];
    const float* etw = (const float*)d_in[8];
    const float* w1  = (const float*)d_in[9];
    const float* w2  = (const float*)d_in[10];
    const float* lnw = (const float*)d_in[11];
    float* out = (float*)d_out;

    float *q_, *mw1_, *mw2_, *hbuf_, *obuf_;
    cudaGetSymbolAddress((void**)&q_, g_q);
    cudaGetSymbolAddress((void**)&mw1_, g_MW1);
    cudaGetSymbolAddress((void**)&mw2_, g_MW2);
    cudaGetSymbolAddress((void**)&hbuf_, g_hbuf);
    cudaGetSymbolAddress((void**)&obuf_, g_obuf);

    init_kernel<<<ID/256, 256>>>(w1, w2, lnw);

    gemm128_proj<<<dim3(4, 16, 3), 256>>>(x, wk, wv, wq);
    gates_kernel<<<Bc*Sc, 128>>>(x, thw, alw, etw);
    act3_kernel<<<3*Bc*Sc, Dc>>>(kn, qn);

    for(int ci=0; ci<NCc; ci++){
        pa_kernel<<<dim3(32,1,4), 256>>>(ci);
        pb_kernel<<<dim3(16,2,4), 256>>>();
        token_kernel<<<dim3(Cc, Bc), Dc>>>(ci);
        pd_kernel<<<dim3(32,1,4), 256>>>();
        rank_ln_kernel<<<516, 256>>>(ci);
    }

    gemm128_gen<<<dim3(8, 4, 4), 256>>>(q_, SD, Dc, mw1_, ID, Dc, hbuf_, SI, Ic, 512, 1);
    gemm128_gen<<<dim3(4, 4, 4), 256>>>(hbuf_, SI, Ic, mw2_, ID, Ic, obuf_, SD, Dc, 1024, 0);
    final_kernel<<<Bc*Sc, Dc>>>(out);
}